// round 8
// baseline (speedup 1.0000x reference)
#include <cuda_runtime.h>

#define NUM_DRUG 50000
#define NUM_CELL 20000
#define HDIM     128
#define NEDGE    600000
#define NBATCH   4096

#define G8_DRUG (NUM_DRUG / 8)   // 6250 warp-tiles
#define G8_CELL (NUM_CELL / 8)   // 2500

#define LAYER_BLOCKS 444         // 3 CTAs/SM x 148 SMs
#define ND_BLOCKS    272         // drug-side share (~61% of work)
#define WARPS        7           // 224 threads / block
#define LAYER_SMEM (HDIM * HDIM * sizeof(float))   // 64 KB: W only, XS eliminated

// ---------------- scratch (device globals; no runtime allocation) ----------
__device__ __align__(16) float g_hA_drug[NUM_DRUG * HDIM];
__device__ __align__(16) float g_hA_cell[NUM_CELL * HDIM];
__device__ __align__(16) float g_hB_drug[NUM_DRUG * HDIM];
__device__ __align__(16) float g_hB_cell[NUM_CELL * HDIM];
__device__ __align__(16) float g_WT_td[HDIM * HDIM];
__device__ __align__(16) float g_WT_dt[HDIM * HDIM];
__device__ int g_off_drug[NUM_DRUG + 1];
__device__ int g_off_cell[NUM_CELL + 1];
__device__ int g_cur_drug[NUM_DRUG];
__device__ int g_cur_cell[NUM_CELL];
__device__ int g_csr_td[NEDGE];
__device__ int g_csr_dt[NEDGE];

// ---------------- f32x2 helpers --------------------------------------------
__device__ __forceinline__ unsigned long long splat2(float x) {
    unsigned long long r; unsigned xi = __float_as_uint(x);
    asm("mov.b64 %0, {%1, %1};" : "=l"(r) : "r"(xi));
    return r;
}
__device__ __forceinline__ unsigned long long pack2(float x, float y) {
    unsigned long long r;
    asm("mov.b64 %0, {%1, %2};" : "=l"(r) : "f"(x), "f"(y));
    return r;
}
__device__ __forceinline__ unsigned long long fma2(unsigned long long a,
                                                   unsigned long long b,
                                                   unsigned long long c) {
    unsigned long long d;
    asm("fma.rn.f32x2 %0, %1, %2, %3;" : "=l"(d) : "l"(a), "l"(b), "l"(c));
    return d;
}
__device__ __forceinline__ float lo2(unsigned long long v) {
    return __uint_as_float((unsigned)(v & 0xffffffffull));
}
__device__ __forceinline__ float hi2(unsigned long long v) {
    return __uint_as_float((unsigned)(v >> 32));
}
__device__ __forceinline__ void add4(float4& a, const float4 b) {
    a.x += b.x; a.y += b.y; a.z += b.z; a.w += b.w;
}

// ---------------- CSR build -------------------------------------------------
__global__ void hist2_kernel(const int* __restrict__ dstA, int* __restrict__ cntA,
                             const int* __restrict__ dstB, int* __restrict__ cntB)
{
    int i = blockIdx.x * blockDim.x + threadIdx.x;
    if (i < NEDGE)               atomicAdd(&cntA[dstA[i]], 1);
    else if (i < 2 * NEDGE)      atomicAdd(&cntB[dstB[i - NEDGE]], 1);
}

// blocks 0,1: coarsened scans. blocks 2,3: weight transposes.
__global__ void scan_transpose_kernel(const int* __restrict__ cntA, int* __restrict__ offA,
                                      const int* __restrict__ cntB, int* __restrict__ offB,
                                      const float* __restrict__ Wa, float* __restrict__ WTa,
                                      const float* __restrict__ Wb, float* __restrict__ WTb)
{
    int t = threadIdx.x;
    if (blockIdx.x >= 2) {
        const float* W = blockIdx.x == 2 ? Wa : Wb;
        float* WT      = blockIdx.x == 2 ? WTa : WTb;
        #pragma unroll
        for (int i = t; i < HDIM * HDIM; i += 1024) {
            int k = i & 127, out = i >> 7;
            WT[k * HDIM + out] = W[out * HDIM + k];
        }
        return;
    }
    const int* cnt = blockIdx.x == 0 ? cntA : cntB;
    int* off       = blockIdx.x == 0 ? offA : offB;
    const int n    = blockIdx.x == 0 ? NUM_DRUG : NUM_CELL;

    __shared__ int ws[32];
    __shared__ int s_carry;
    int lane = t & 31, w = t >> 5;
    if (t == 0) s_carry = 0;
    __syncthreads();

    for (int base = 0; base < n; base += 1024 * 8) {
        int idx = base + t * 8;
        int v[8];
        #pragma unroll
        for (int j = 0; j < 8; j++)
            v[j] = (idx + j < n) ? cnt[idx + j] : 0;
        #pragma unroll
        for (int j = 1; j < 8; j++) v[j] += v[j - 1];
        int tot = v[7];
        int x = tot;
        #pragma unroll
        for (int o = 1; o < 32; o <<= 1) {
            int y = __shfl_up_sync(0xffffffffu, x, o);
            if (lane >= o) x += y;
        }
        if (lane == 31) ws[w] = x;
        __syncthreads();
        if (w == 0) {
            int s = ws[lane];
            #pragma unroll
            for (int o = 1; o < 32; o <<= 1) {
                int y = __shfl_up_sync(0xffffffffu, s, o);
                if (lane >= o) s += y;
            }
            ws[lane] = s;
        }
        __syncthreads();
        int prefix = (x - tot) + (w ? ws[w - 1] : 0) + s_carry;
        #pragma unroll
        for (int j = 0; j < 8; j++)
            if (idx + j < n) off[idx + j + 1] = prefix + v[j];
        __syncthreads();
        if (t == 0) s_carry += ws[31];
        __syncthreads();
    }
    if (t == 0) off[0] = 0;
}

__global__ void fill2_kernel(const int* __restrict__ srcA, const int* __restrict__ dstA,
                             const int* __restrict__ offA, int* __restrict__ curA,
                             int* __restrict__ csrA,
                             const int* __restrict__ srcB, const int* __restrict__ dstB,
                             const int* __restrict__ offB, int* __restrict__ curB,
                             int* __restrict__ csrB)
{
    int tid = blockIdx.x * blockDim.x + threadIdx.x;
    int i0 = tid * 2;
    if (i0 < NEDGE) {
        int i1 = i0 + 1;
        int d0 = dstA[i0];
        int d1 = (i1 < NEDGE) ? dstA[i1] : -1;
        int s0 = srcA[i0];
        int s1 = (i1 < NEDGE) ? srcA[i1] : 0;
        int p0 = offA[d0] + atomicAdd(&curA[d0], 1);
        int p1 = (d1 >= 0) ? (offA[d1] + atomicAdd(&curA[d1], 1)) : 0;
        csrA[p0] = s0;
        if (d1 >= 0) csrA[p1] = s1;
    } else if (i0 < 2 * NEDGE) {
        int j0 = i0 - NEDGE, j1 = j0 + 1;
        int d0 = dstB[j0];
        int d1 = (j1 < NEDGE) ? dstB[j1] : -1;
        int s0 = srcB[j0];
        int s1 = (j1 < NEDGE) ? srcB[j1] : 0;
        int p0 = offB[d0] + atomicAdd(&curB[d0], 1);
        int p1 = (d1 >= 0) ? (offB[d1] + atomicAdd(&curB[d1], 1)) : 0;
        csrB[p0] = s0;
        if (d1 >= 0) csrB[p1] = s1;
    }
}

// ---------------- layer: gather-mean -> shuffle-GEMM -> res -> LN -> ReLU --
__global__ void __launch_bounds__(224, 3)
layer_kernel(const float* __restrict__ hd_in, const float* __restrict__ hc_in,
             float* __restrict__ hd_out, float* __restrict__ hc_out,
             const float* __restrict__ WT_td, const float* __restrict__ WT_dt,
             const float* __restrict__ gd, const float* __restrict__ bd,
             const float* __restrict__ gc, const float* __restrict__ bc,
             const int* __restrict__ off_d, const int* __restrict__ csr_d,
             const int* __restrict__ off_c, const int* __restrict__ csr_c)
{
    const bool isD = blockIdx.x < ND_BLOCKS;
    const float* src  = isD ? hc_in : hd_in;
    const float* hold = isD ? hd_in : hc_in;
    float* outp       = isD ? hd_out : hc_out;
    const float* WTg  = isD ? WT_td : WT_dt;
    const float* gam  = isD ? gd : gc;
    const float* bet  = isD ? bd : bc;
    const int* off    = isD ? off_d : off_c;
    const int* csr    = isD ? csr_d : csr_c;
    const int ng8     = isD ? G8_DRUG : G8_CELL;
    const int nb      = isD ? ND_BLOCKS : (LAYER_BLOCKS - ND_BLOCKS);
    const int bid     = isD ? blockIdx.x : blockIdx.x - ND_BLOCKS;

    extern __shared__ float WT[];                    // [128][128] fp32, 64 KB
    const int t = threadIdx.x, lane = t & 31, w = t >> 5;
    const int c0 = 4 * lane;

    {
        const float4* s4 = reinterpret_cast<const float4*>(WTg);
        float4* d4 = reinterpret_cast<float4*>(WT);
        for (int i = t; i < HDIM * HDIM / 4; i += 224) d4[i] = s4[i];
    }
    __syncthreads();

    const float4* src4  = reinterpret_cast<const float4*>(src);
    const float4* hold4 = reinterpret_cast<const float4*>(hold);
    float4* out4        = reinterpret_cast<float4*>(outp);
    const float4* gam4  = reinterpret_cast<const float4*>(gam);
    const float4* bet4  = reinterpret_cast<const float4*>(bet);

    for (int wg = bid * WARPS + w; wg < ng8; wg += nb * WARPS) {
        const int row0 = wg * 8;

        // ---- gather-mean 8 rows into registers (lane holds k = 4L..4L+3) --
        unsigned long long axy[8], azw[8];
        #pragma unroll
        for (int i = 0; i < 8; i++) {
            int r = row0 + i;
            int jb = off[r], je = off[r + 1];
            float4 a0 = {0,0,0,0}, a1 = {0,0,0,0}, a2 = {0,0,0,0}, a3 = {0,0,0,0};
            int j = jb;
            for (; j + 8 <= je; j += 8) {
                int s0 = csr[j],   s1 = csr[j+1], s2 = csr[j+2], s3 = csr[j+3];
                int s4 = csr[j+4], s5 = csr[j+5], s6 = csr[j+6], s7 = csr[j+7];
                float4 v0 = src4[s0 * 32 + lane];
                float4 v1 = src4[s1 * 32 + lane];
                float4 v2 = src4[s2 * 32 + lane];
                float4 v3 = src4[s3 * 32 + lane];
                float4 v4 = src4[s4 * 32 + lane];
                float4 v5 = src4[s5 * 32 + lane];
                float4 v6 = src4[s6 * 32 + lane];
                float4 v7 = src4[s7 * 32 + lane];
                add4(a0, v0); add4(a1, v1); add4(a2, v2); add4(a3, v3);
                add4(a0, v4); add4(a1, v5); add4(a2, v6); add4(a3, v7);
            }
            if (j + 4 <= je) {
                int s0 = csr[j], s1 = csr[j+1], s2 = csr[j+2], s3 = csr[j+3];
                float4 v0 = src4[s0 * 32 + lane];
                float4 v1 = src4[s1 * 32 + lane];
                float4 v2 = src4[s2 * 32 + lane];
                float4 v3 = src4[s3 * 32 + lane];
                add4(a0, v0); add4(a1, v1); add4(a2, v2); add4(a3, v3);
                j += 4;
            }
            for (; j < je; j++) {
                float4 v = src4[csr[j] * 32 + lane];
                add4(a0, v);
            }
            a0.x += a1.x + a2.x + a3.x;
            a0.y += a1.y + a2.y + a3.y;
            a0.z += a1.z + a2.z + a3.z;
            a0.w += a1.w + a2.w + a3.w;
            int deg = je - jb;
            float inv = 1.0f / (float)(deg < 1 ? 1 : deg);
            axy[i] = pack2(a0.x * inv, a0.y * inv);
            azw[i] = pack2(a0.z * inv, a0.w * inv);
        }

        // ---- shuffle-GEMM: y[i][c0..c0+3] = sum_k x[i][k] * W[k][c] -------
        unsigned long long acc2[8][2];
        #pragma unroll
        for (int i = 0; i < 8; i++) { acc2[i][0] = 0ull; acc2[i][1] = 0ull; }

        #pragma unroll 4
        for (int S = 0; S < 32; S++) {
            // W rows k = 4S..4S+3, this lane's 4 output columns
            ulonglong2 w0 = *reinterpret_cast<const ulonglong2*>(&WT[(4*S+0) * HDIM + c0]);
            ulonglong2 w1 = *reinterpret_cast<const ulonglong2*>(&WT[(4*S+1) * HDIM + c0]);
            ulonglong2 w2 = *reinterpret_cast<const ulonglong2*>(&WT[(4*S+2) * HDIM + c0]);
            ulonglong2 w3 = *reinterpret_cast<const ulonglong2*>(&WT[(4*S+3) * HDIM + c0]);
            #pragma unroll
            for (int i = 0; i < 8; i++) {
                unsigned long long xlo = __shfl_sync(0xffffffffu, axy[i], S);
                unsigned long long xhi = __shfl_sync(0xffffffffu, azw[i], S);
                acc2[i][0] = fma2(splat2(lo2(xlo)), w0.x, acc2[i][0]);
                acc2[i][1] = fma2(splat2(lo2(xlo)), w0.y, acc2[i][1]);
                acc2[i][0] = fma2(splat2(hi2(xlo)), w1.x, acc2[i][0]);
                acc2[i][1] = fma2(splat2(hi2(xlo)), w1.y, acc2[i][1]);
                acc2[i][0] = fma2(splat2(lo2(xhi)), w2.x, acc2[i][0]);
                acc2[i][1] = fma2(splat2(lo2(xhi)), w2.y, acc2[i][1]);
                acc2[i][0] = fma2(splat2(hi2(xhi)), w3.x, acc2[i][0]);
                acc2[i][1] = fma2(splat2(hi2(xhi)), w3.y, acc2[i][1]);
            }
        }

        // ---- epilogue: residual + LayerNorm + ReLU ----
        const float4 g4 = __ldg(&gam4[lane]);
        const float4 b4 = __ldg(&bet4[lane]);
        #pragma unroll
        for (int i = 0; i < 8; i++) {
            int grow = row0 + i;
            float4 hv = hold4[grow * 32 + lane];
            float y0 = lo2(acc2[i][0]) + hv.x;
            float y1 = hi2(acc2[i][0]) + hv.y;
            float y2 = lo2(acc2[i][1]) + hv.z;
            float y3 = hi2(acc2[i][1]) + hv.w;

            float s = y0 + y1 + y2 + y3;
            float q = y0*y0 + y1*y1 + y2*y2 + y3*y3;
            #pragma unroll
            for (int o = 16; o; o >>= 1) {
                s += __shfl_xor_sync(0xffffffffu, s, o);
                q += __shfl_xor_sync(0xffffffffu, q, o);
            }
            float mu  = s * (1.0f / HDIM);
            float var = q * (1.0f / HDIM) - mu * mu;
            float rs  = rsqrtf(var + 1e-5f);
            float4 o4;
            o4.x = (y0 - mu) * rs * g4.x + b4.x; o4.x = o4.x > 0.f ? o4.x : 0.f;
            o4.y = (y1 - mu) * rs * g4.y + b4.y; o4.y = o4.y > 0.f ? o4.y : 0.f;
            o4.z = (y2 - mu) * rs * g4.z + b4.z; o4.z = o4.z > 0.f ? o4.z : 0.f;
            o4.w = (y3 - mu) * rs * g4.w + b4.w; o4.w = o4.w > 0.f ? o4.w : 0.f;
            out4[grow * 32 + lane] = o4;
        }
    }
}

// ---------------- final head -------------------------------------------------
__global__ void final_kernel(const float* __restrict__ hd,
                             const float* __restrict__ hc,
                             const int* __restrict__ did,
                             const int* __restrict__ cid,
                             const float* __restrict__ wf,
                             const float* __restrict__ bf,
                             float* __restrict__ out, int nb)
{
    int warp = (blockIdx.x * blockDim.x + threadIdx.x) >> 5;
    int lane = threadIdx.x & 31;
    if (warp >= nb) return;
    int d = did[warp], c = cid[warp];
    float4 a  = reinterpret_cast<const float4*>(hd)[d * 32 + lane];
    float4 w1 = reinterpret_cast<const float4*>(wf)[lane];
    float4 b4 = reinterpret_cast<const float4*>(hc)[c * 32 + lane];
    float4 w2 = reinterpret_cast<const float4*>(wf)[32 + lane];
    float s = a.x * w1.x + a.y * w1.y + a.z * w1.z + a.w * w1.w
            + b4.x * w2.x + b4.y * w2.y + b4.z * w2.z + b4.w * w2.w;
    #pragma unroll
    for (int o = 16; o; o >>= 1) s += __shfl_xor_sync(0xffffffffu, s, o);
    if (lane == 0) {
        float x = s + bf[0];
        out[warp] = 1.0f / (1.0f + expf(-x));
    }
}

// ---------------------------------------------------------------------------
extern "C" void kernel_launch(void* const* d_in, const int* in_sizes, int n_in,
                              void* d_out, int out_size)
{
    const float* emb_drug  = (const float*)d_in[0];
    const float* emb_cell  = (const float*)d_in[1];
    const float* W_dt      = (const float*)d_in[2];
    const float* W_td      = (const float*)d_in[3];
    const float* ln_drug_g = (const float*)d_in[4];
    const float* ln_drug_b = (const float*)d_in[5];
    const float* ln_cell_g = (const float*)d_in[6];
    const float* ln_cell_b = (const float*)d_in[7];
    const float* W_final_w = (const float*)d_in[8];
    const float* W_final_b = (const float*)d_in[9];
    const int* edge_dt_src = (const int*)d_in[10];
    const int* edge_dt_dst = (const int*)d_in[11];
    const int* edge_td_src = (const int*)d_in[12];
    const int* edge_td_dst = (const int*)d_in[13];
    const int* drug_ids    = (const int*)d_in[14];
    const int* cell_ids    = (const int*)d_in[15];
    float* out = (float*)d_out;

    float *hA_d, *hA_c, *hB_d, *hB_c, *WT_td, *WT_dt;
    int *off_d, *off_c, *cur_d, *cur_c, *csr_td, *csr_dt;
    cudaGetSymbolAddress((void**)&hA_d,   g_hA_drug);
    cudaGetSymbolAddress((void**)&hA_c,   g_hA_cell);
    cudaGetSymbolAddress((void**)&hB_d,   g_hB_drug);
    cudaGetSymbolAddress((void**)&hB_c,   g_hB_cell);
    cudaGetSymbolAddress((void**)&WT_td,  g_WT_td);
    cudaGetSymbolAddress((void**)&WT_dt,  g_WT_dt);
    cudaGetSymbolAddress((void**)&off_d,  g_off_drug);
    cudaGetSymbolAddress((void**)&off_c,  g_off_cell);
    cudaGetSymbolAddress((void**)&cur_d,  g_cur_drug);
    cudaGetSymbolAddress((void**)&cur_c,  g_cur_cell);
    cudaGetSymbolAddress((void**)&csr_td, g_csr_td);
    cudaGetSymbolAddress((void**)&csr_dt, g_csr_dt);

    cudaFuncSetAttribute(layer_kernel,
                         cudaFuncAttributeMaxDynamicSharedMemorySize,
                         (int)LAYER_SMEM);

    const int eb2 = (2 * NEDGE + 255) / 256;

    // ---------------- CSR build ----------------
    cudaMemsetAsync(cur_d, 0, NUM_DRUG * sizeof(int));
    cudaMemsetAsync(cur_c, 0, NUM_CELL * sizeof(int));
    hist2_kernel<<<eb2, 256>>>(edge_td_dst, cur_d, edge_dt_dst, cur_c);
    scan_transpose_kernel<<<4, 1024>>>(cur_d, off_d, cur_c, off_c,
                                       W_td, WT_td, W_dt, WT_dt);
    cudaMemsetAsync(cur_d, 0, NUM_DRUG * sizeof(int));
    cudaMemsetAsync(cur_c, 0, NUM_CELL * sizeof(int));
    fill2_kernel<<<(NEDGE + 255) / 256, 256>>>(
        edge_td_src, edge_td_dst, off_d, cur_d, csr_td,
        edge_dt_src, edge_dt_dst, off_c, cur_c, csr_dt);

    // ---------------- layers ----------------
    layer_kernel<<<LAYER_BLOCKS, 224, LAYER_SMEM>>>(
        emb_drug, emb_cell, hA_d, hA_c, WT_td, WT_dt,
        ln_drug_g, ln_drug_b, ln_cell_g, ln_cell_b,
        off_d, csr_td, off_c, csr_dt);
    layer_kernel<<<LAYER_BLOCKS, 224, LAYER_SMEM>>>(
        hA_d, hA_c, hB_d, hB_c, WT_td, WT_dt,
        ln_drug_g, ln_drug_b, ln_cell_g, ln_cell_b,
        off_d, csr_td, off_c, csr_dt);

    // ---------------- final head ----------------
    final_kernel<<<(NBATCH * 32) / 256, 256>>>(hB_d, hB_c, drug_ids, cell_ids,
                                               W_final_w, W_final_b, out, NBATCH);
}

// round 9
// speedup vs baseline: 1.4629x; 1.4629x over previous
#include <cuda_runtime.h>

#define NUM_DRUG 50000
#define NUM_CELL 20000
#define HDIM     128
#define NEDGE    600000
#define NBATCH   4096

#define G8_DRUG (NUM_DRUG / 8)   // 6250 warp-tiles
#define G8_CELL (NUM_CELL / 8)   // 2500

#define GEMM_BLOCKS 296
#define ND_BLOCKS   212          // drug share of gemm blocks (50k/70k rows)
#define WARPS       8            // 256 threads / block
#define GEMM_SMEM ((HDIM * HDIM + WARPS * 8 * HDIM) * sizeof(float))  // 96 KB

// ---------------- scratch (device globals; no runtime allocation) ----------
__device__ __align__(16) float g_hA_drug[NUM_DRUG * HDIM];
__device__ __align__(16) float g_hA_cell[NUM_CELL * HDIM];
__device__ __align__(16) float g_hB_drug[NUM_DRUG * HDIM];
__device__ __align__(16) float g_hB_cell[NUM_CELL * HDIM];
__device__ __align__(16) float g_acc[(NUM_DRUG + NUM_CELL) * HDIM];  // mean msgs
__device__ __align__(16) float g_WT_td[HDIM * HDIM];
__device__ __align__(16) float g_WT_dt[HDIM * HDIM];
__device__ int g_off_drug[NUM_DRUG + 1];
__device__ int g_off_cell[NUM_CELL + 1];
__device__ int g_cur_drug[NUM_DRUG];
__device__ int g_cur_cell[NUM_CELL];
__device__ int g_csr_td[NEDGE];
__device__ int g_csr_dt[NEDGE];

// ---------------- f32x2 helpers --------------------------------------------
__device__ __forceinline__ unsigned long long splat2(float x) {
    unsigned long long r; unsigned xi = __float_as_uint(x);
    asm("mov.b64 %0, {%1, %1};" : "=l"(r) : "r"(xi));
    return r;
}
__device__ __forceinline__ unsigned long long fma2(unsigned long long a,
                                                   unsigned long long b,
                                                   unsigned long long c) {
    unsigned long long d;
    asm("fma.rn.f32x2 %0, %1, %2, %3;" : "=l"(d) : "l"(a), "l"(b), "l"(c));
    return d;
}
__device__ __forceinline__ float lo2(unsigned long long v) {
    return __uint_as_float((unsigned)(v & 0xffffffffull));
}
__device__ __forceinline__ float hi2(unsigned long long v) {
    return __uint_as_float((unsigned)(v >> 32));
}
__device__ __forceinline__ void add4(float4& a, const float4 b) {
    a.x += b.x; a.y += b.y; a.z += b.z; a.w += b.w;
}

// ---------------- CSR build -------------------------------------------------
__global__ void hist2_kernel(const int* __restrict__ dstA, int* __restrict__ cntA,
                             const int* __restrict__ dstB, int* __restrict__ cntB)
{
    int i = blockIdx.x * blockDim.x + threadIdx.x;
    if (i < NEDGE)               atomicAdd(&cntA[dstA[i]], 1);
    else if (i < 2 * NEDGE)      atomicAdd(&cntB[dstB[i - NEDGE]], 1);
}

// blocks 0,1: coarsened scans. blocks 2,3: weight transposes.
__global__ void scan_transpose_kernel(const int* __restrict__ cntA, int* __restrict__ offA,
                                      const int* __restrict__ cntB, int* __restrict__ offB,
                                      const float* __restrict__ Wa, float* __restrict__ WTa,
                                      const float* __restrict__ Wb, float* __restrict__ WTb)
{
    int t = threadIdx.x;
    if (blockIdx.x >= 2) {
        const float* W = blockIdx.x == 2 ? Wa : Wb;
        float* WT      = blockIdx.x == 2 ? WTa : WTb;
        #pragma unroll
        for (int i = t; i < HDIM * HDIM; i += 1024) {
            int k = i & 127, out = i >> 7;
            WT[k * HDIM + out] = W[out * HDIM + k];
        }
        return;
    }
    const int* cnt = blockIdx.x == 0 ? cntA : cntB;
    int* off       = blockIdx.x == 0 ? offA : offB;
    const int n    = blockIdx.x == 0 ? NUM_DRUG : NUM_CELL;

    __shared__ int ws[32];
    __shared__ int s_carry;
    int lane = t & 31, w = t >> 5;
    if (t == 0) s_carry = 0;
    __syncthreads();

    for (int base = 0; base < n; base += 1024 * 8) {
        int idx = base + t * 8;
        int v[8];
        #pragma unroll
        for (int j = 0; j < 8; j++)
            v[j] = (idx + j < n) ? cnt[idx + j] : 0;
        #pragma unroll
        for (int j = 1; j < 8; j++) v[j] += v[j - 1];
        int tot = v[7];
        int x = tot;
        #pragma unroll
        for (int o = 1; o < 32; o <<= 1) {
            int y = __shfl_up_sync(0xffffffffu, x, o);
            if (lane >= o) x += y;
        }
        if (lane == 31) ws[w] = x;
        __syncthreads();
        if (w == 0) {
            int s = ws[lane];
            #pragma unroll
            for (int o = 1; o < 32; o <<= 1) {
                int y = __shfl_up_sync(0xffffffffu, s, o);
                if (lane >= o) s += y;
            }
            ws[lane] = s;
        }
        __syncthreads();
        int prefix = (x - tot) + (w ? ws[w - 1] : 0) + s_carry;
        #pragma unroll
        for (int j = 0; j < 8; j++)
            if (idx + j < n) off[idx + j + 1] = prefix + v[j];
        __syncthreads();
        if (t == 0) s_carry += ws[31];
        __syncthreads();
    }
    if (t == 0) off[0] = 0;
}

__global__ void fill2_kernel(const int* __restrict__ srcA, const int* __restrict__ dstA,
                             const int* __restrict__ offA, int* __restrict__ curA,
                             int* __restrict__ csrA,
                             const int* __restrict__ srcB, const int* __restrict__ dstB,
                             const int* __restrict__ offB, int* __restrict__ curB,
                             int* __restrict__ csrB)
{
    int tid = blockIdx.x * blockDim.x + threadIdx.x;
    int i0 = tid * 2;
    if (i0 < NEDGE) {
        int i1 = i0 + 1;
        int d0 = dstA[i0];
        int d1 = (i1 < NEDGE) ? dstA[i1] : -1;
        int s0 = srcA[i0];
        int s1 = (i1 < NEDGE) ? srcA[i1] : 0;
        int p0 = offA[d0] + atomicAdd(&curA[d0], 1);
        int p1 = (d1 >= 0) ? (offA[d1] + atomicAdd(&curA[d1], 1)) : 0;
        csrA[p0] = s0;
        if (d1 >= 0) csrA[p1] = s1;
    } else if (i0 < 2 * NEDGE) {
        int j0 = i0 - NEDGE, j1 = j0 + 1;
        int d0 = dstB[j0];
        int d1 = (j1 < NEDGE) ? dstB[j1] : -1;
        int s0 = srcB[j0];
        int s1 = (j1 < NEDGE) ? srcB[j1] : 0;
        int p0 = offB[d0] + atomicAdd(&curB[d0], 1);
        int p1 = (d1 >= 0) ? (offB[d1] + atomicAdd(&curB[d1], 1)) : 0;
        csrB[p0] = s0;
        if (d1 >= 0) csrB[p1] = s1;
    }
}

// ---------------- gather-mean: one warp per dst row, both sides ------------
// Low regs, no smem -> high occupancy; hides L2 latency.
__global__ void __launch_bounds__(256)
gather_kernel(const float* __restrict__ hd_in, const float* __restrict__ hc_in,
              float* __restrict__ acc,
              const int* __restrict__ off_d, const int* __restrict__ csr_d,
              const int* __restrict__ off_c, const int* __restrict__ csr_c)
{
    const int gw   = (blockIdx.x * blockDim.x + threadIdx.x) >> 5;  // row id
    const int lane = threadIdx.x & 31;
    const bool isD = gw < NUM_DRUG;
    const float* src = isD ? hc_in : hd_in;
    const int* off   = isD ? off_d : off_c;
    const int* csr   = isD ? csr_d : csr_c;
    const int r      = isD ? gw : gw - NUM_DRUG;

    const float4* src4 = reinterpret_cast<const float4*>(src);
    int jb = off[r], je = off[r + 1];
    float4 a0 = {0,0,0,0}, a1 = {0,0,0,0}, a2 = {0,0,0,0}, a3 = {0,0,0,0};
    int j = jb;
    for (; j + 8 <= je; j += 8) {
        int s0 = csr[j],   s1 = csr[j+1], s2 = csr[j+2], s3 = csr[j+3];
        int s4 = csr[j+4], s5 = csr[j+5], s6 = csr[j+6], s7 = csr[j+7];
        float4 v0 = src4[s0 * 32 + lane];
        float4 v1 = src4[s1 * 32 + lane];
        float4 v2 = src4[s2 * 32 + lane];
        float4 v3 = src4[s3 * 32 + lane];
        float4 v4 = src4[s4 * 32 + lane];
        float4 v5 = src4[s5 * 32 + lane];
        float4 v6 = src4[s6 * 32 + lane];
        float4 v7 = src4[s7 * 32 + lane];
        add4(a0, v0); add4(a1, v1); add4(a2, v2); add4(a3, v3);
        add4(a0, v4); add4(a1, v5); add4(a2, v6); add4(a3, v7);
    }
    if (j + 4 <= je) {
        int s0 = csr[j], s1 = csr[j+1], s2 = csr[j+2], s3 = csr[j+3];
        float4 v0 = src4[s0 * 32 + lane];
        float4 v1 = src4[s1 * 32 + lane];
        float4 v2 = src4[s2 * 32 + lane];
        float4 v3 = src4[s3 * 32 + lane];
        add4(a0, v0); add4(a1, v1); add4(a2, v2); add4(a3, v3);
        j += 4;
    }
    for (; j < je; j++) add4(a0, src4[csr[j] * 32 + lane]);

    a0.x += a1.x + a2.x + a3.x;
    a0.y += a1.y + a2.y + a3.y;
    a0.z += a1.z + a2.z + a3.z;
    a0.w += a1.w + a2.w + a3.w;
    int deg = je - jb;
    float inv = 1.0f / (float)(deg < 1 ? 1 : deg);
    a0.x *= inv; a0.y *= inv; a0.z *= inv; a0.w *= inv;
    reinterpret_cast<float4*>(acc)[gw * 32 + lane] = a0;
}

// ---------------- GEMM + residual + LN + ReLU (R7 GEMM structure) ----------
__global__ void __launch_bounds__(256, 2)
gemm_ln_kernel(const float* __restrict__ acc,           // [70000][128] means
               const float* __restrict__ hd_in, const float* __restrict__ hc_in,
               float* __restrict__ hd_out, float* __restrict__ hc_out,
               const float* __restrict__ WT_td, const float* __restrict__ WT_dt,
               const float* __restrict__ gd, const float* __restrict__ bd,
               const float* __restrict__ gc, const float* __restrict__ bc)
{
    const bool isD = blockIdx.x < ND_BLOCKS;
    const float* accp = isD ? acc : acc + (size_t)NUM_DRUG * HDIM;
    const float* hold = isD ? hd_in : hc_in;
    float* outp       = isD ? hd_out : hc_out;
    const float* WTg  = isD ? WT_td : WT_dt;
    const float* gam  = isD ? gd : gc;
    const float* bet  = isD ? bd : bc;
    const int ng8     = isD ? G8_DRUG : G8_CELL;
    const int nb      = isD ? ND_BLOCKS : (GEMM_BLOCKS - ND_BLOCKS);
    const int bid     = isD ? blockIdx.x : blockIdx.x - ND_BLOCKS;

    extern __shared__ float sm[];
    float* WT = sm;                                  // [128][128]
    const int t = threadIdx.x, lane = t & 31, w = t >> 5;
    float* XS = sm + HDIM * HDIM + w * (8 * HDIM);   // warp-private [8][128]
    const int c0 = 4 * lane;

    {
        const float4* s4 = reinterpret_cast<const float4*>(WTg);
        float4* d4 = reinterpret_cast<float4*>(WT);
        #pragma unroll
        for (int i = t; i < HDIM * HDIM / 4; i += 256) d4[i] = s4[i];
    }
    const float4 g4 = reinterpret_cast<const float4*>(gam)[lane];
    const float4 b4 = reinterpret_cast<const float4*>(bet)[lane];
    __syncthreads();

    const float4* acc4  = reinterpret_cast<const float4*>(accp);
    const float4* hold4 = reinterpret_cast<const float4*>(hold);
    float4* out4        = reinterpret_cast<float4*>(outp);

    for (int wg = bid * WARPS + w; wg < ng8; wg += nb * WARPS) {
        const int row0 = wg * 8;

        // ---- load 8 mean rows into XS (coalesced) ----
        #pragma unroll
        for (int i = 0; i < 8; i++)
            *reinterpret_cast<float4*>(&XS[i * HDIM + c0]) = acc4[(row0 + i) * 32 + lane];
        __syncwarp();

        // ---- GEMM: y[i][out] = sum_k x[i][k] * W[out][k], f32x2 packed ----
        unsigned long long acc2[8][2];
        #pragma unroll
        for (int i = 0; i < 8; i++) { acc2[i][0] = 0ull; acc2[i][1] = 0ull; }

        for (int kt = 0; kt < HDIM; kt += 4) {
            float4 xv[8];
            #pragma unroll
            for (int i = 0; i < 8; i++)
                xv[i] = *reinterpret_cast<const float4*>(&XS[i * HDIM + kt]);
            #pragma unroll
            for (int kk = 0; kk < 4; kk++) {
                ulonglong2 wv = *reinterpret_cast<const ulonglong2*>(
                    &WT[(kt + kk) * HDIM + c0]);
                #pragma unroll
                for (int i = 0; i < 8; i++) {
                    float xs = (kk == 0) ? xv[i].x : (kk == 1) ? xv[i].y
                             : (kk == 2) ? xv[i].z : xv[i].w;
                    unsigned long long s2 = splat2(xs);
                    acc2[i][0] = fma2(s2, wv.x, acc2[i][0]);
                    acc2[i][1] = fma2(s2, wv.y, acc2[i][1]);
                }
            }
        }

        // ---- epilogue: residual + LayerNorm + ReLU ----
        #pragma unroll
        for (int i = 0; i < 8; i++) {
            int grow = row0 + i;
            float4 hv = hold4[grow * 32 + lane];
            float y0 = lo2(acc2[i][0]) + hv.x;
            float y1 = hi2(acc2[i][0]) + hv.y;
            float y2 = lo2(acc2[i][1]) + hv.z;
            float y3 = hi2(acc2[i][1]) + hv.w;

            float s = y0 + y1 + y2 + y3;
            float q = y0*y0 + y1*y1 + y2*y2 + y3*y3;
            #pragma unroll
            for (int o = 16; o; o >>= 1) {
                s += __shfl_xor_sync(0xffffffffu, s, o);
                q += __shfl_xor_sync(0xffffffffu, q, o);
            }
            float mu  = s * (1.0f / HDIM);
            float var = q * (1.0f / HDIM) - mu * mu;
            float rs  = rsqrtf(var + 1e-5f);
            float4 o4;
            o4.x = (y0 - mu) * rs * g4.x + b4.x; o4.x = o4.x > 0.f ? o4.x : 0.f;
            o4.y = (y1 - mu) * rs * g4.y + b4.y; o4.y = o4.y > 0.f ? o4.y : 0.f;
            o4.z = (y2 - mu) * rs * g4.z + b4.z; o4.z = o4.z > 0.f ? o4.z : 0.f;
            o4.w = (y3 - mu) * rs * g4.w + b4.w; o4.w = o4.w > 0.f ? o4.w : 0.f;
            out4[grow * 32 + lane] = o4;
        }
        __syncwarp();   // XS reused next iteration
    }
}

// ---------------- final head -------------------------------------------------
__global__ void final_kernel(const float* __restrict__ hd,
                             const float* __restrict__ hc,
                             const int* __restrict__ did,
                             const int* __restrict__ cid,
                             const float* __restrict__ wf,
                             const float* __restrict__ bf,
                             float* __restrict__ out, int nb)
{
    int warp = (blockIdx.x * blockDim.x + threadIdx.x) >> 5;
    int lane = threadIdx.x & 31;
    if (warp >= nb) return;
    int d = did[warp], c = cid[warp];
    float4 a  = reinterpret_cast<const float4*>(hd)[d * 32 + lane];
    float4 w1 = reinterpret_cast<const float4*>(wf)[lane];
    float4 b4 = reinterpret_cast<const float4*>(hc)[c * 32 + lane];
    float4 w2 = reinterpret_cast<const float4*>(wf)[32 + lane];
    float s = a.x * w1.x + a.y * w1.y + a.z * w1.z + a.w * w1.w
            + b4.x * w2.x + b4.y * w2.y + b4.z * w2.z + b4.w * w2.w;
    #pragma unroll
    for (int o = 16; o; o >>= 1) s += __shfl_xor_sync(0xffffffffu, s, o);
    if (lane == 0) {
        float x = s + bf[0];
        out[warp] = 1.0f / (1.0f + expf(-x));
    }
}

// ---------------------------------------------------------------------------
extern "C" void kernel_launch(void* const* d_in, const int* in_sizes, int n_in,
                              void* d_out, int out_size)
{
    const float* emb_drug  = (const float*)d_in[0];
    const float* emb_cell  = (const float*)d_in[1];
    const float* W_dt      = (const float*)d_in[2];
    const float* W_td      = (const float*)d_in[3];
    const float* ln_drug_g = (const float*)d_in[4];
    const float* ln_drug_b = (const float*)d_in[5];
    const float* ln_cell_g = (const float*)d_in[6];
    const float* ln_cell_b = (const float*)d_in[7];
    const float* W_final_w = (const float*)d_in[8];
    const float* W_final_b = (const float*)d_in[9];
    const int* edge_dt_src = (const int*)d_in[10];
    const int* edge_dt_dst = (const int*)d_in[11];
    const int* edge_td_src = (const int*)d_in[12];
    const int* edge_td_dst = (const int*)d_in[13];
    const int* drug_ids    = (const int*)d_in[14];
    const int* cell_ids    = (const int*)d_in[15];
    float* out = (float*)d_out;

    float *hA_d, *hA_c, *hB_d, *hB_c, *accb, *WT_td, *WT_dt;
    int *off_d, *off_c, *cur_d, *cur_c, *csr_td, *csr_dt;
    cudaGetSymbolAddress((void**)&hA_d,   g_hA_drug);
    cudaGetSymbolAddress((void**)&hA_c,   g_hA_cell);
    cudaGetSymbolAddress((void**)&hB_d,   g_hB_drug);
    cudaGetSymbolAddress((void**)&hB_c,   g_hB_cell);
    cudaGetSymbolAddress((void**)&accb,   g_acc);
    cudaGetSymbolAddress((void**)&WT_td,  g_WT_td);
    cudaGetSymbolAddress((void**)&WT_dt,  g_WT_dt);
    cudaGetSymbolAddress((void**)&off_d,  g_off_drug);
    cudaGetSymbolAddress((void**)&off_c,  g_off_cell);
    cudaGetSymbolAddress((void**)&cur_d,  g_cur_drug);
    cudaGetSymbolAddress((void**)&cur_c,  g_cur_cell);
    cudaGetSymbolAddress((void**)&csr_td, g_csr_td);
    cudaGetSymbolAddress((void**)&csr_dt, g_csr_dt);

    cudaFuncSetAttribute(gemm_ln_kernel,
                         cudaFuncAttributeMaxDynamicSharedMemorySize,
                         (int)GEMM_SMEM);

    const int eb2 = (2 * NEDGE + 255) / 256;
    const int gather_blocks = (NUM_DRUG + NUM_CELL) / 8;   // 8750

    // ---------------- CSR build ----------------
    cudaMemsetAsync(cur_d, 0, NUM_DRUG * sizeof(int));
    cudaMemsetAsync(cur_c, 0, NUM_CELL * sizeof(int));
    hist2_kernel<<<eb2, 256>>>(edge_td_dst, cur_d, edge_dt_dst, cur_c);
    scan_transpose_kernel<<<4, 1024>>>(cur_d, off_d, cur_c, off_c,
                                       W_td, WT_td, W_dt, WT_dt);
    cudaMemsetAsync(cur_d, 0, NUM_DRUG * sizeof(int));
    cudaMemsetAsync(cur_c, 0, NUM_CELL * sizeof(int));
    fill2_kernel<<<(NEDGE + 255) / 256, 256>>>(
        edge_td_src, edge_td_dst, off_d, cur_d, csr_td,
        edge_dt_src, edge_dt_dst, off_c, cur_c, csr_dt);

    // ---------------- layer 0 ----------------
    gather_kernel<<<gather_blocks, 256>>>(emb_drug, emb_cell, accb,
                                          off_d, csr_td, off_c, csr_dt);
    gemm_ln_kernel<<<GEMM_BLOCKS, 256, GEMM_SMEM>>>(
        accb, emb_drug, emb_cell, hA_d, hA_c, WT_td, WT_dt,
        ln_drug_g, ln_drug_b, ln_cell_g, ln_cell_b);

    // ---------------- layer 1 ----------------
    gather_kernel<<<gather_blocks, 256>>>(hA_d, hA_c, accb,
                                          off_d, csr_td, off_c, csr_dt);
    gemm_ln_kernel<<<GEMM_BLOCKS, 256, GEMM_SMEM>>>(
        accb, hA_d, hA_c, hB_d, hB_c, WT_td, WT_dt,
        ln_drug_g, ln_drug_b, ln_cell_g, ln_cell_b);

    // ---------------- final head ----------------
    final_kernel<<<(NBATCH * 32) / 256, 256>>>(hB_d, hB_c, drug_ids, cell_ids,
                                               W_final_w, W_final_b, out, NBATCH);
}